// round 13
// baseline (speedup 1.0000x reference)
#include <cuda_runtime.h>
#include <cuda_fp16.h>
#include <cstdint>
#include <cstddef>

#define BATCH 4
#define C_IN  64
#define O_OUT 64
#define H_DIM 128
#define W_DIM 128

// ---------------- device scratch ----------------
// y = x*f(alpha), pixel-major [b][h][w][c], single fp16 plane
__device__ __align__(1024) __half g_y[BATCH * H_DIM * W_DIM * C_IN];
// weights fp16: [tap(9)][o(64)][c(64)]
__device__ __align__(1024) __half g_w[9 * 64 * 64];

// ---------------- helpers ----------------
__device__ __forceinline__ uint32_t smem_u32(const void* p) {
    uint32_t a;
    asm("{ .reg .u64 t; cvta.to.shared.u64 t, %1; cvt.u32.u64 %0, t; }"
        : "=r"(a) : "l"(p));
    return a;
}
__device__ __forceinline__ void st128(uint32_t dst, uint4 v) {
    asm volatile("st.shared.v4.b32 [%0], {%1,%2,%3,%4};"
                 :: "r"(dst), "r"(v.x), "r"(v.y), "r"(v.z), "r"(v.w) : "memory");
}
__device__ __forceinline__ void cp16(uint32_t dst, const void* src) {
    asm volatile("cp.async.cg.shared.global [%0], [%1], 16;"
                 :: "r"(dst), "l"(__cvta_generic_to_global(src)) : "memory");
}
__device__ __forceinline__ void cp_commit() {
    asm volatile("cp.async.commit_group;" ::: "memory");
}
__device__ __forceinline__ void cp_wait1() {
    asm volatile("cp.async.wait_group 1;" ::: "memory");
}
__device__ __forceinline__ void cp_wait0() {
    asm volatile("cp.async.wait_group 0;" ::: "memory");
}
__device__ __forceinline__ void ldsm_x4(uint32_t* r, uint32_t addr) {
    asm volatile("ldmatrix.sync.aligned.m8n8.x4.shared.b16 {%0,%1,%2,%3}, [%4];"
                 : "=r"(r[0]), "=r"(r[1]), "=r"(r[2]), "=r"(r[3]) : "r"(addr));
}
__device__ __forceinline__ void mma16816(float* c, const uint32_t* a, const uint32_t* b) {
    asm volatile(
        "mma.sync.aligned.m16n8k16.row.col.f32.f16.f16.f32 "
        "{%0,%1,%2,%3}, {%4,%5,%6,%7}, {%8,%9}, {%0,%1,%2,%3};"
        : "+f"(c[0]), "+f"(c[1]), "+f"(c[2]), "+f"(c[3])
        : "r"(a[0]), "r"(a[1]), "r"(a[2]), "r"(a[3]), "r"(b[0]), "r"(b[1]));
}

// ------- K1: weights fp16 (blocks 0..143) + y = x*f(alpha) transpose fp16 -------
__global__ __launch_bounds__(256)
void prep_kernel(const float* __restrict__ x, const float* __restrict__ alpha,
                 const float* __restrict__ wgt,
                 const float* __restrict__ pa, const float* __restrict__ pb,
                 const float* __restrict__ pc)
{
    __shared__ __align__(16) float fa[128];
    __shared__ __align__(16) float ysm[64][132];
    const int bid = blockIdx.x, b = bid >> 7, h = bid & 127;
    const int tid = threadIdx.x;
    const float ka = *pa, kb = *pb, kc = *pc;

    if (bid < 144) {   // folded wprep: 36864 weight elements
        const int e = bid * 256 + tid;
        const int o = e / 576, r = e % 576, c = r / 9, tap = r % 9;
        g_w[((size_t)tap * 64 + o) * 64 + c] = __float2half(wgt[e]);
    }

    if (tid < 128) {
        const float av = alpha[(b * 128 + h) * 128 + tid];
        fa[tid] = (ka * av + kb) * av + kc;
    }
    __syncthreads();
    {
        const int c = tid >> 2, seg = (tid & 3) * 32;
        const float4* xr = (const float4*)(x + (((size_t)(b * 64 + c) * 128 + h) * 128 + seg));
        const float4* fr = (const float4*)(fa + seg);
        #pragma unroll
        for (int i = 0; i < 8; i++) {
            const float4 xv = xr[i], fv = fr[i];
            ysm[c][seg + 4 * i + 0] = xv.x * fv.x;
            ysm[c][seg + 4 * i + 1] = xv.y * fv.y;
            ysm[c][seg + 4 * i + 2] = xv.z * fv.z;
            ysm[c][seg + 4 * i + 3] = xv.w * fv.w;
        }
    }
    __syncthreads();
    if (tid < 128) {
        const int w = tid;
        uint32_t buf[32];
        #pragma unroll
        for (int p = 0; p < 32; p++) {
            const __half h0 = __float2half(ysm[2 * p][w]);
            const __half h1 = __float2half(ysm[2 * p + 1][w]);
            buf[p] = (uint32_t)__half_as_ushort(h0) |
                     ((uint32_t)__half_as_ushort(h1) << 16);
        }
        uint4* dst = (uint4*)(g_y + ((size_t)((b * 128 + h) * 128 + w)) * 64);
        #pragma unroll
        for (int j = 0; j < 8; j++)
            dst[j] = make_uint4(buf[4*j], buf[4*j+1], buf[4*j+2], buf[4*j+3]);
    }
}

// ---------------- K2: conv, cp.async multistage, single fp16 term ----------------
// Unit: A = 130 rows x 80B (K-half, 32c), B = 3 dj tiles x 64 rows x 80B.
#define ASTR 80
#define APL  (130 * 80)              // 10400
#define BOFF APL
#define BTL  (64 * 80)               // 5120
#define UNIT (BOFF + 3 * BTL)        // 25760
#define SMEM_TOTAL (2 * UNIT)        // 51520 -> 4 CTAs/SM

__global__ __launch_bounds__(256, 4)
void conv_kernel(const float* __restrict__ bias, float* __restrict__ out)
{
    extern __shared__ __align__(128) unsigned char smem[];
    const uint32_t sb = smem_u32(smem);
    const int tid = threadIdx.x, lane = tid & 31, wid = tid >> 5;
    const int bid = blockIdx.x, b = bid >> 7, h = bid & 127;
    const int m0 = (wid >> 1) * 32, n0 = (wid & 1) * 32;

    float acc[2][4][4] = {};

    const int t8 = lane >> 3, r8 = lane & 7;
    const int a_row  = ((t8 & 1) << 3) + r8;
    const int a_koff = (t8 >> 1) << 3;
    const int b_orow = ((t8 >> 1) << 3) + r8;
    const int b_koff = (t8 & 1) << 3;

    // zero A halo rows (0,129) in both buffers
    if (tid < 16) {
        const int ch = tid & 3, row = ((tid >> 2) & 1) ? 129 : 0;
        const int bufi = tid >> 3;
        st128(sb + (uint32_t)bufi * UNIT + (uint32_t)row * ASTR + ch * 16,
              make_uint4(0u, 0u, 0u, 0u));
    }
    __syncthreads();

    // valid units: (di, kh)
    int ulist[6], nunits = 0;
    #pragma unroll
    for (int di = 0; di < 3; di++) {
        const int hs = h + di - 1;
        if ((unsigned)hs < 128u) { ulist[nunits++] = di * 2; ulist[nunits++] = di * 2 + 1; }
    }

    auto issue_unit = [&](int code, uint32_t bufbase) {
        const int di = code >> 1, kh = code & 1;
        const int hs = h + di - 1;
        // A: 512 tasks: ch(4) x w(128)
        #pragma unroll
        for (int it = 0; it < 2; it++) {
            const int task = tid + it * 256;
            const int ch = task & 3, w = task >> 2;
            cp16(bufbase + (uint32_t)(w + 1) * ASTR + ch * 16,
                 (const uint4*)(g_y + ((size_t)((b * 128 + hs) * 128 + w)) * 64) +
                     (kh * 4 + ch));
        }
        // B: 768 tasks: ch(4) x o(64) x dj(3)
        #pragma unroll
        for (int it = 0; it < 3; it++) {
            const int task = tid + it * 256;
            const int ch = task & 3, o = (task >> 2) & 63, dj = task >> 8;
            cp16(bufbase + BOFF + (uint32_t)dj * BTL + (uint32_t)o * ASTR + ch * 16,
                 (const uint4*)(g_w + ((size_t)((di * 3 + dj) * 64 + o)) * 64) +
                     (kh * 4 + ch));
        }
        cp_commit();
    };

    issue_unit(ulist[0], sb);
    if (nunits > 1) issue_unit(ulist[1], sb + UNIT);

    #pragma unroll 1
    for (int u = 0; u < nunits; u++) {
        if (u + 1 < nunits) cp_wait1(); else cp_wait0();
        __syncthreads();

        const uint32_t bufbase = sb + (uint32_t)(u & 1) * UNIT;
        #pragma unroll 1
        for (int dj = 0; dj < 3; dj++) {
            const uint32_t bb = bufbase + BOFF + (uint32_t)dj * BTL;
            #pragma unroll
            for (int k0 = 0; k0 < 32; k0 += 16) {
                uint32_t af[2][4], bf[2][4];
                #pragma unroll
                for (int mi = 0; mi < 2; mi++)
                    ldsm_x4(af[mi], bufbase +
                        (uint32_t)(m0 + mi * 16 + a_row + dj) * ASTR +
                        (uint32_t)(k0 + a_koff) * 2);
                #pragma unroll
                for (int ni = 0; ni < 2; ni++)
                    ldsm_x4(bf[ni], bb +
                        (uint32_t)(n0 + ni * 16 + b_orow) * ASTR +
                        (uint32_t)(k0 + b_koff) * 2);
                #pragma unroll
                for (int mi = 0; mi < 2; mi++)
                    #pragma unroll
                    for (int nj = 0; nj < 4; nj++)
                        mma16816(acc[mi][nj], af[mi], &bf[nj >> 1][(nj & 1) * 2]);
            }
        }
        __syncthreads();
        if (u + 2 < nunits) issue_unit(ulist[u + 2], bufbase);
    }

    // ---- epilogue ----
    const int orow = lane >> 2, opair = (lane & 3) * 2;
    #pragma unroll
    for (int nj = 0; nj < 4; nj++) {
        const int o = n0 + nj * 8 + opair;
        const float bv0 = bias[o], bv1 = bias[o + 1];
        float* p0 = out + (((size_t)(b * 64 + o)) * 128 + h) * 128;
        float* p1 = p0 + 128 * 128;
        #pragma unroll
        for (int mi = 0; mi < 2; mi++) {
            const int w = m0 + mi * 16 + orow;
            p0[w]     = acc[mi][nj][0] + bv0;
            p1[w]     = acc[mi][nj][1] + bv1;
            p0[w + 8] = acc[mi][nj][2] + bv0;
            p1[w + 8] = acc[mi][nj][3] + bv1;
        }
    }
}

extern "C" void kernel_launch(void* const* d_in, const int* in_sizes, int n_in,
                              void* d_out, int out_size)
{
    const float* x     = (const float*)d_in[0];  // [4,64,128,128]
    const float* alpha = (const float*)d_in[1];  // [4,1,128,128]
    const float* wgt   = (const float*)d_in[2];  // [64,64,3,3]
    const float* bias  = (const float*)d_in[3];  // [64]
    const float* pa    = (const float*)d_in[4];
    const float* pb    = (const float*)d_in[5];
    const float* pc    = (const float*)d_in[6];
    float* out = (float*)d_out;                  // [4,64,128,128]

    cudaFuncSetAttribute(conv_kernel,
                         cudaFuncAttributeMaxDynamicSharedMemorySize, SMEM_TOTAL);

    prep_kernel<<<BATCH * H_DIM, 256>>>(x, alpha, wgt, pa, pb, pc);
    conv_kernel<<<BATCH * H_DIM, 256, SMEM_TOTAL>>>(bias, out);
}

// round 15
// speedup vs baseline: 1.6070x; 1.6070x over previous
#include <cuda_runtime.h>
#include <cuda_fp16.h>
#include <cstdint>
#include <cstddef>

#define BATCH 4
#define C_IN  64
#define O_OUT 64
#define H_DIM 128
#define W_DIM 128

// ---------------- device scratch ----------------
// y = x*f(alpha), pixel-major [b][h][w][c], single fp16 plane
__device__ __align__(1024) __half g_y[BATCH * H_DIM * W_DIM * C_IN];
// weights fp16: [tap(9)][o(64)][c(64)]
__device__ __align__(1024) __half g_w[9 * 64 * 64];

// ---------------- helpers ----------------
__device__ __forceinline__ uint32_t smem_u32(const void* p) {
    uint32_t a;
    asm("{ .reg .u64 t; cvta.to.shared.u64 t, %1; cvt.u32.u64 %0, t; }"
        : "=r"(a) : "l"(p));
    return a;
}
__device__ __forceinline__ void st128(uint32_t dst, uint4 v) {
    asm volatile("st.shared.v4.b32 [%0], {%1,%2,%3,%4};"
                 :: "r"(dst), "r"(v.x), "r"(v.y), "r"(v.z), "r"(v.w) : "memory");
}
__device__ __forceinline__ void cp16(uint32_t dst, const void* src) {
    asm volatile("cp.async.cg.shared.global [%0], [%1], 16;"
                 :: "r"(dst), "l"(__cvta_generic_to_global(src)) : "memory");
}
__device__ __forceinline__ void cp_commit() {
    asm volatile("cp.async.commit_group;" ::: "memory");
}
__device__ __forceinline__ void cp_wait1() {
    asm volatile("cp.async.wait_group 1;" ::: "memory");
}
__device__ __forceinline__ void cp_wait0() {
    asm volatile("cp.async.wait_group 0;" ::: "memory");
}
__device__ __forceinline__ void ldsm_x4(uint32_t* r, uint32_t addr) {
    asm volatile("ldmatrix.sync.aligned.m8n8.x4.shared.b16 {%0,%1,%2,%3}, [%4];"
                 : "=r"(r[0]), "=r"(r[1]), "=r"(r[2]), "=r"(r[3]) : "r"(addr));
}
__device__ __forceinline__ void mma16816(float* c, const uint32_t* a, const uint32_t* b) {
    asm volatile(
        "mma.sync.aligned.m16n8k16.row.col.f32.f16.f16.f32 "
        "{%0,%1,%2,%3}, {%4,%5,%6,%7}, {%8,%9}, {%0,%1,%2,%3};"
        : "+f"(c[0]), "+f"(c[1]), "+f"(c[2]), "+f"(c[3])
        : "r"(a[0]), "r"(a[1]), "r"(a[2]), "r"(a[3]), "r"(b[0]), "r"(b[1]));
}

// ------- K1: weights fp16 (blocks 0..143) + y = x*f(alpha) transpose fp16 -------
__global__ __launch_bounds__(256)
void prep_kernel(const float* __restrict__ x, const float* __restrict__ alpha,
                 const float* __restrict__ wgt,
                 const float* __restrict__ pa, const float* __restrict__ pb,
                 const float* __restrict__ pc)
{
    __shared__ __align__(16) float fa[128];
    __shared__ __align__(16) float ysm[64][132];
    const int bid = blockIdx.x, b = bid >> 7, h = bid & 127;
    const int tid = threadIdx.x;
    const float ka = *pa, kb = *pb, kc = *pc;

    if (bid < 144) {   // folded wprep: 36864 weight elements
        const int e = bid * 256 + tid;
        const int o = e / 576, r = e % 576, c = r / 9, tap = r % 9;
        g_w[((size_t)tap * 64 + o) * 64 + c] = __float2half(wgt[e]);
    }

    if (tid < 128) {
        const float av = alpha[(b * 128 + h) * 128 + tid];
        fa[tid] = (ka * av + kb) * av + kc;
    }
    __syncthreads();
    {
        const int c = tid >> 2, seg = (tid & 3) * 32;
        const float4* xr = (const float4*)(x + (((size_t)(b * 64 + c) * 128 + h) * 128 + seg));
        const float4* fr = (const float4*)(fa + seg);
        #pragma unroll
        for (int i = 0; i < 8; i++) {
            const float4 xv = xr[i], fv = fr[i];
            ysm[c][seg + 4 * i + 0] = xv.x * fv.x;
            ysm[c][seg + 4 * i + 1] = xv.y * fv.y;
            ysm[c][seg + 4 * i + 2] = xv.z * fv.z;
            ysm[c][seg + 4 * i + 3] = xv.w * fv.w;
        }
    }
    __syncthreads();
    if (tid < 128) {
        const int w = tid;
        uint32_t buf[32];
        #pragma unroll
        for (int p = 0; p < 32; p++) {
            const __half h0 = __float2half(ysm[2 * p][w]);
            const __half h1 = __float2half(ysm[2 * p + 1][w]);
            buf[p] = (uint32_t)__half_as_ushort(h0) |
                     ((uint32_t)__half_as_ushort(h1) << 16);
        }
        uint4* dst = (uint4*)(g_y + ((size_t)((b * 128 + h) * 128 + w)) * 64);
        #pragma unroll
        for (int j = 0; j < 8; j++)
            dst[j] = make_uint4(buf[4*j], buf[4*j+1], buf[4*j+2], buf[4*j+3]);
    }
}

// ---------------- K2: conv, 2 output rows per CTA, cp.async multistage ----------------
// Unit (di, kh): A = 2 row-planes x 130 x 80B (32c half), B = 3 dj tiles x 64 x 80B.
#define ASTR 80
#define APL  (130 * 80)              // 10400 per row plane
#define BOFF (2 * APL)               // 20800
#define BTL  (64 * 80)               // 5120
#define UNIT (BOFF + 3 * BTL)        // 36160
#define SMEM_TOTAL (2 * UNIT)        // 72320 -> 2 CTAs/SM

__global__ __launch_bounds__(256, 2)
void conv_kernel(const float* __restrict__ bias, float* __restrict__ out)
{
    extern __shared__ __align__(128) unsigned char smem[];
    const uint32_t sb = smem_u32(smem);
    const int tid = threadIdx.x, lane = tid & 31, wid = tid >> 5;
    const int bid = blockIdx.x, b = bid >> 6, hp = bid & 63;   // 256 CTAs

    // warp tile: 64(m) x 32(n); wid -> (row-plane, pixel-base, n0)
    const int mrow = wid >> 2;                 // A plane 0/1 (output row)
    const int mloc = ((wid >> 1) & 1) * 64;    // pixel base within row
    const int n0   = (wid & 1) * 32;

    float acc[4][4][4] = {};                   // [mi][nj][frag]

    const int t8 = lane >> 3, r8 = lane & 7;
    const int a_row  = ((t8 & 1) << 3) + r8;
    const int a_koff = (t8 >> 1) << 3;
    const int b_orow = ((t8 >> 1) << 3) + r8;
    const int b_koff = (t8 & 1) << 3;

    // zero A halo cols (0,129) of both planes in both buffers: 32 st128
    if (tid < 32) {
        const int ch = tid & 3, col = ((tid >> 2) & 1) ? 129 : 0;
        const int pl = (tid >> 3) & 1, bufi = tid >> 4;
        st128(sb + (uint32_t)bufi * UNIT + (uint32_t)pl * APL +
              (uint32_t)col * ASTR + ch * 16, make_uint4(0u, 0u, 0u, 0u));
    }
    __syncthreads();

    // stage unit u (di = u>>1, kh = u&1) into a buffer
    auto issue_unit = [&](int u, uint32_t bufbase) {
        const int di = u >> 1, kh = u & 1;
        #pragma unroll
        for (int pl = 0; pl < 2; pl++) {
            const int hs = 2 * hp - 1 + di + pl;
            const uint32_t abase = bufbase + (uint32_t)pl * APL;
            if ((unsigned)hs < 128u) {
                #pragma unroll
                for (int it = 0; it < 2; it++) {
                    const int task = tid + it * 256;
                    const int ch = task & 3, w = task >> 2;
                    cp16(abase + (uint32_t)(w + 1) * ASTR + ch * 16,
                         (const uint4*)(g_y +
                             ((size_t)((b * 128 + hs) * 128 + w)) * 64) + (kh * 4 + ch));
                }
            } else {   // zero-fill out-of-range input row
                #pragma unroll
                for (int it = 0; it < 2; it++) {
                    const int task = tid + it * 256;
                    const int ch = task & 3, w = task >> 2;
                    st128(abase + (uint32_t)(w + 1) * ASTR + ch * 16,
                          make_uint4(0u, 0u, 0u, 0u));
                }
            }
        }
        // B: 768 tasks: ch(4) x o(64) x dj(3)
        #pragma unroll
        for (int it = 0; it < 3; it++) {
            const int task = tid + it * 256;
            const int ch = task & 3, o = (task >> 2) & 63, dj = task >> 8;
            cp16(bufbase + BOFF + (uint32_t)dj * BTL + (uint32_t)o * ASTR + ch * 16,
                 (const uint4*)(g_w + ((size_t)((di * 3 + dj) * 64 + o)) * 64) +
                     (kh * 4 + ch));
        }
        cp_commit();
    };

    issue_unit(0, sb);
    issue_unit(1, sb + UNIT);

    #pragma unroll 1
    for (int u = 0; u < 6; u++) {
        if (u < 5) cp_wait1(); else cp_wait0();
        __syncthreads();

        const uint32_t bufbase = sb + (uint32_t)(u & 1) * UNIT;
        const uint32_t abase = bufbase + (uint32_t)mrow * APL;
        #pragma unroll 1
        for (int dj = 0; dj < 3; dj++) {
            const uint32_t bb = bufbase + BOFF + (uint32_t)dj * BTL;
            #pragma unroll
            for (int k0 = 0; k0 < 32; k0 += 16) {
                uint32_t af[4][4], bf[2][4];
                #pragma unroll
                for (int mi = 0; mi < 4; mi++)
                    ldsm_x4(af[mi], abase +
                        (uint32_t)(mloc + mi * 16 + a_row + dj) * ASTR +
                        (uint32_t)(k0 + a_koff) * 2);
                #pragma unroll
                for (int ni = 0; ni < 2; ni++)
                    ldsm_x4(bf[ni], bb +
                        (uint32_t)(n0 + ni * 16 + b_orow) * ASTR +
                        (uint32_t)(k0 + b_koff) * 2);
                #pragma unroll
                for (int mi = 0; mi < 4; mi++)
                    #pragma unroll
                    for (int nj = 0; nj < 4; nj++)
                        mma16816(acc[mi][nj], af[mi], &bf[nj >> 1][(nj & 1) * 2]);
            }
        }
        __syncthreads();
        if (u + 2 < 6) issue_unit(u + 2, bufbase);
    }

    // ---- epilogue ----
    const int hout = 2 * hp + mrow;
    const int orow = lane >> 2, opair = (lane & 3) * 2;
    #pragma unroll
    for (int nj = 0; nj < 4; nj++) {
        const int o = n0 + nj * 8 + opair;
        const float bv0 = bias[o], bv1 = bias[o + 1];
        float* p0 = out + (((size_t)(b * 64 + o)) * 128 + hout) * 128;
        float* p1 = p0 + 128 * 128;
        #pragma unroll
        for (int mi = 0; mi < 4; mi++) {
            const int w = mloc + mi * 16 + orow;
            p0[w]     = acc[mi][nj][0] + bv0;
            p1[w]     = acc[mi][nj][1] + bv1;
            p0[w + 8] = acc[mi][nj][2] + bv0;
            p1[w + 8] = acc[mi][nj][3] + bv1;
        }
    }
}

extern "C" void kernel_launch(void* const* d_in, const int* in_sizes, int n_in,
                              void* d_out, int out_size)
{
    const float* x     = (const float*)d_in[0];  // [4,64,128,128]
    const float* alpha = (const float*)d_in[1];  // [4,1,128,128]
    const float* wgt   = (const float*)d_in[2];  // [64,64,3,3]
    const float* bias  = (const float*)d_in[3];  // [64]
    const float* pa    = (const float*)d_in[4];
    const float* pb    = (const float*)d_in[5];
    const float* pc    = (const float*)d_in[6];
    float* out = (float*)d_out;                  // [4,64,128,128]

    cudaFuncSetAttribute(conv_kernel,
                         cudaFuncAttributeMaxDynamicSharedMemorySize, SMEM_TOTAL);

    prep_kernel<<<BATCH * H_DIM, 256>>>(x, alpha, wgt, pa, pb, pc);
    conv_kernel<<<BATCH * (H_DIM / 2), 256, SMEM_TOTAL>>>(bias, out);
}

// round 16
// speedup vs baseline: 1.7199x; 1.0703x over previous
#include <cuda_runtime.h>
#include <cuda_fp16.h>
#include <cstdint>
#include <cstddef>

#define BATCH 4
#define C_IN  64
#define O_OUT 64
#define H_DIM 128
#define W_DIM 128

// ---------------- device scratch ----------------
// y = x*f(alpha), pixel-major [b][h][w][c], single fp16 plane
__device__ __align__(1024) __half g_y[BATCH * H_DIM * W_DIM * C_IN];
// weights fp16: [tap(9)][o(64)][c(64)]
__device__ __align__(1024) __half g_w[9 * 64 * 64];

// ---------------- helpers ----------------
__device__ __forceinline__ uint32_t smem_u32(const void* p) {
    uint32_t a;
    asm("{ .reg .u64 t; cvta.to.shared.u64 t, %1; cvt.u32.u64 %0, t; }"
        : "=r"(a) : "l"(p));
    return a;
}
__device__ __forceinline__ void st128(uint32_t dst, uint4 v) {
    asm volatile("st.shared.v4.b32 [%0], {%1,%2,%3,%4};"
                 :: "r"(dst), "r"(v.x), "r"(v.y), "r"(v.z), "r"(v.w) : "memory");
}
__device__ __forceinline__ void cp16(uint32_t dst, const void* src) {
    asm volatile("cp.async.cg.shared.global [%0], [%1], 16;"
                 :: "r"(dst), "l"(__cvta_generic_to_global(src)) : "memory");
}
__device__ __forceinline__ void cp_commit() {
    asm volatile("cp.async.commit_group;" ::: "memory");
}
__device__ __forceinline__ void cp_wait1() {
    asm volatile("cp.async.wait_group 1;" ::: "memory");
}
__device__ __forceinline__ void cp_wait0() {
    asm volatile("cp.async.wait_group 0;" ::: "memory");
}
__device__ __forceinline__ void ldsm_x4(uint32_t* r, uint32_t addr) {
    asm volatile("ldmatrix.sync.aligned.m8n8.x4.shared.b16 {%0,%1,%2,%3}, [%4];"
                 : "=r"(r[0]), "=r"(r[1]), "=r"(r[2]), "=r"(r[3]) : "r"(addr));
}
__device__ __forceinline__ void mma16816(float* c, const uint32_t* a, const uint32_t* b) {
    asm volatile(
        "mma.sync.aligned.m16n8k16.row.col.f32.f16.f16.f32 "
        "{%0,%1,%2,%3}, {%4,%5,%6,%7}, {%8,%9}, {%0,%1,%2,%3};"
        : "+f"(c[0]), "+f"(c[1]), "+f"(c[2]), "+f"(c[3])
        : "r"(a[0]), "r"(a[1]), "r"(a[2]), "r"(a[3]), "r"(b[0]), "r"(b[1]));
}

// ------- K1: weights fp16 (blocks 0..143) + y = x*f(alpha) transpose fp16 -------
__global__ __launch_bounds__(256)
void prep_kernel(const float* __restrict__ x, const float* __restrict__ alpha,
                 const float* __restrict__ wgt,
                 const float* __restrict__ pa, const float* __restrict__ pb,
                 const float* __restrict__ pc)
{
    __shared__ __align__(16) float fa[128];
    __shared__ __align__(16) float ysm[64][132];
    const int bid = blockIdx.x, b = bid >> 7, h = bid & 127;
    const int tid = threadIdx.x;
    const float ka = *pa, kb = *pb, kc = *pc;

    if (bid < 144) {   // folded wprep: 36864 weight elements
        const int e = bid * 256 + tid;
        const int o = e / 576, r = e % 576, c = r / 9, tap = r % 9;
        g_w[((size_t)tap * 64 + o) * 64 + c] = __float2half(wgt[e]);
    }

    if (tid < 128) {
        const float av = alpha[(b * 128 + h) * 128 + tid];
        fa[tid] = (ka * av + kb) * av + kc;
    }
    __syncthreads();
    {
        const int c = tid >> 2, seg = (tid & 3) * 32;
        const float4* xr = (const float4*)(x + (((size_t)(b * 64 + c) * 128 + h) * 128 + seg));
        const float4* fr = (const float4*)(fa + seg);
        #pragma unroll
        for (int i = 0; i < 8; i++) {
            const float4 xv = xr[i], fv = fr[i];
            ysm[c][seg + 4 * i + 0] = xv.x * fv.x;
            ysm[c][seg + 4 * i + 1] = xv.y * fv.y;
            ysm[c][seg + 4 * i + 2] = xv.z * fv.z;
            ysm[c][seg + 4 * i + 3] = xv.w * fv.w;
        }
    }
    __syncthreads();
    {   // all 256 threads: w = tid>>1, each writes 64B (16 c-pairs)
        const int w = tid >> 1, half = tid & 1;
        uint32_t buf[16];
        #pragma unroll
        for (int q = 0; q < 16; q++) {
            const int p = half * 16 + q;
            const __half h0 = __float2half(ysm[2 * p][w]);
            const __half h1 = __float2half(ysm[2 * p + 1][w]);
            buf[q] = (uint32_t)__half_as_ushort(h0) |
                     ((uint32_t)__half_as_ushort(h1) << 16);
        }
        uint4* dst = (uint4*)(g_y + ((size_t)((b * 128 + h) * 128 + w)) * 64 + half * 32);
        #pragma unroll
        for (int j = 0; j < 4; j++)
            dst[j] = make_uint4(buf[4*j], buf[4*j+1], buf[4*j+2], buf[4*j+3]);
    }
}

// ---------------- K2: conv, 4 output rows per CTA, 2-unit (K-half) pipeline ----------------
// Unit (kh): A = 6 input-row planes x 130 x 80B (32c half), B = 9 tap tiles x 64 x 80B.
#define ASTR 80
#define APL  (130 * 80)              // 10400 per input-row plane
#define BOFF (6 * APL)               // 62400
#define BTL  (64 * 80)               // 5120
#define UNIT (BOFF + 9 * BTL)        // 108480
#define SMEM_TOTAL (2 * UNIT)        // 216960 (<227KB) -> 1 CTA/SM

__global__ __launch_bounds__(512, 1)
void conv_kernel(const float* __restrict__ bias, float* __restrict__ out)
{
    extern __shared__ __align__(128) unsigned char smem[];
    const uint32_t sb = smem_u32(smem);
    const int tid = threadIdx.x, lane = tid & 31, wid = tid >> 5;
    const int bid = blockIdx.x, b = bid >> 5, hq = bid & 31;   // 128 CTAs

    // 16 warps: warp tile 64(m) x 32(n) on output row (4hq + mrow)
    const int mrow = wid >> 2;                 // output row within quad (0..3)
    const int mloc = ((wid >> 1) & 1) * 64;    // pixel base
    const int n0   = (wid & 1) * 32;

    float acc[4][4][4] = {};                   // [mi][nj][frag]

    const int t8 = lane >> 3, r8 = lane & 7;
    const int a_row  = ((t8 & 1) << 3) + r8;
    const int a_koff = (t8 >> 1) << 3;
    const int b_orow = ((t8 >> 1) << 3) + r8;
    const int b_koff = (t8 & 1) << 3;

    // zero A halo cols (w=0 and w=129) of all 6 planes in both buffers: 96 st128
    if (tid < 96) {
        const int ch = tid & 3, q = tid >> 2;        // q = 0..23
        const int col = (q & 1) ? 129 : 0;
        const int q2 = q >> 1;                       // 0..11
        const int pl = q2 % 6, bufi = q2 / 6;
        st128(sb + (uint32_t)bufi * UNIT + (uint32_t)pl * APL +
              (uint32_t)col * ASTR + ch * 16, make_uint4(0u, 0u, 0u, 0u));
    }
    __syncthreads();

    // stage unit kh into a buffer: 6 A planes (input rows 4hq-1 .. 4hq+4) + 9 B tiles
    auto issue_unit = [&](int kh, uint32_t bufbase) {
        const int ch = tid & 3, w = tid >> 2;        // 512 tasks per plane
        #pragma unroll
        for (int pl = 0; pl < 6; pl++) {
            const int hs = 4 * hq - 1 + pl;
            const uint32_t dst = bufbase + (uint32_t)pl * APL +
                                 (uint32_t)(w + 1) * ASTR + ch * 16;
            if ((unsigned)hs < 128u)
                cp16(dst, (const uint4*)(g_y +
                     ((size_t)((b * 128 + hs) * 128 + w)) * 64) + (kh * 4 + ch));
            else
                st128(dst, make_uint4(0u, 0u, 0u, 0u));
        }
        // B: 2304 tasks: ch(4) x o(64) x tap(9)
        #pragma unroll
        for (int it = 0; it < 5; it++) {
            const int task = tid + it * 512;
            if (task < 2304) {
                const int bch = task & 3, o = (task >> 2) & 63, tap = task >> 8;
                cp16(bufbase + BOFF + (uint32_t)tap * BTL +
                         (uint32_t)o * ASTR + bch * 16,
                     (const uint4*)(g_w + ((size_t)(tap * 64 + o)) * 64) +
                         (kh * 4 + bch));
            }
        }
        cp_commit();
    };

    issue_unit(0, sb);
    issue_unit(1, sb + UNIT);

    #pragma unroll 1
    for (int u = 0; u < 2; u++) {
        if (u == 0) cp_wait1(); else cp_wait0();
        __syncthreads();

        const uint32_t bufbase = sb + (uint32_t)u * UNIT;
        #pragma unroll 1
        for (int di = 0; di < 3; di++) {
            const uint32_t abase = bufbase + (uint32_t)(mrow + di) * APL;
            #pragma unroll 1
            for (int dj = 0; dj < 3; dj++) {
                const uint32_t bb = bufbase + BOFF + (uint32_t)(di * 3 + dj) * BTL;
                #pragma unroll
                for (int k0 = 0; k0 < 32; k0 += 16) {
                    uint32_t af[4][4], bf[2][4];
                    #pragma unroll
                    for (int mi = 0; mi < 4; mi++)
                        ldsm_x4(af[mi], abase +
                            (uint32_t)(mloc + mi * 16 + a_row + dj) * ASTR +
                            (uint32_t)(k0 + a_koff) * 2);
                    #pragma unroll
                    for (int ni = 0; ni < 2; ni++)
                        ldsm_x4(bf[ni], bb +
                            (uint32_t)(n0 + ni * 16 + b_orow) * ASTR +
                            (uint32_t)(k0 + b_koff) * 2);
                    #pragma unroll
                    for (int mi = 0; mi < 4; mi++)
                        #pragma unroll
                        for (int nj = 0; nj < 4; nj++)
                            mma16816(acc[mi][nj], af[mi], &bf[nj >> 1][(nj & 1) * 2]);
                }
            }
        }
        if (u == 0) __syncthreads();   // protect buffer 0? (not reused) — keep order cheap
    }

    // ---- epilogue ----
    const int hout = 4 * hq + mrow;
    const int orow = lane >> 2, opair = (lane & 3) * 2;
    #pragma unroll
    for (int nj = 0; nj < 4; nj++) {
        const int o = n0 + nj * 8 + opair;
        const float bv0 = bias[o], bv1 = bias[o + 1];
        float* p0 = out + (((size_t)(b * 64 + o)) * 128 + hout) * 128;
        float* p1 = p0 + 128 * 128;
        #pragma unroll
        for (int mi = 0; mi < 4; mi++) {
            const int w = mloc + mi * 16 + orow;
            p0[w]     = acc[mi][nj][0] + bv0;
            p1[w]     = acc[mi][nj][1] + bv1;
            p0[w + 8] = acc[mi][nj][2] + bv0;
            p1[w + 8] = acc[mi][nj][3] + bv1;
        }
    }
}

extern "C" void kernel_launch(void* const* d_in, const int* in_sizes, int n_in,
                              void* d_out, int out_size)
{
    const float* x     = (const float*)d_in[0];  // [4,64,128,128]
    const float* alpha = (const float*)d_in[1];  // [4,1,128,128]
    const float* wgt   = (const float*)d_in[2];  // [64,64,3,3]
    const float* bias  = (const float*)d_in[3];  // [64]
    const float* pa    = (const float*)d_in[4];
    const float* pb    = (const float*)d_in[5];
    const float* pc    = (const float*)d_in[6];
    float* out = (float*)d_out;                  // [4,64,128,128]

    cudaFuncSetAttribute(conv_kernel,
                         cudaFuncAttributeMaxDynamicSharedMemorySize, SMEM_TOTAL);

    prep_kernel<<<BATCH * H_DIM, 256>>>(x, alpha, wgt, pa, pb, pc);
    conv_kernel<<<BATCH * (H_DIM / 4), 512, SMEM_TOTAL>>>(bias, out);
}